// round 15
// baseline (speedup 1.0000x reference)
#include <cuda_runtime.h>

#define NN 50000
#define NE 800000
#define C 64
#define CIN 16
#define NL 4
#define HSTEP 0.1f
#define EPSV 1e-3f

// ---- static device scratch ----
__device__ __align__(256) float g_Xn[NN * C];
__device__ __align__(256) float g_Zs[(size_t)NL * NN * C];  // per-layer Z
__device__ __align__(256) float g_W[NN * C];
__device__ __align__(256) float g_U[NN * C];
__device__ __align__(256) float g_div[NN * C];      // running divergence (64ch)
__device__ __align__(256) float g_div16[NN * CIN];  // raw-xe divergence (16ch)
__device__ __align__(256) float g_scr[6 * C];
__device__ __align__(256) float g_nrm[6 * C];
__device__ __align__(256) float g_nrmA[NL * 2 * C];
__device__ __align__(256) float g_M2[CIN * CIN];
// CSR
#define NBLK ((NN + 255) / 256)   // 196
__device__ int g_deg[NN];
__device__ int g_w[NN];
__device__ int g_off[NN + 1];
__device__ int g_cur[NN];
__device__ int g_adj[2 * NE];
__device__ int g_bsum[NBLK];
__device__ int g_boff[NBLK];

__device__ __forceinline__ void red4(float* p, float x, float y, float z, float w) {
    asm volatile("red.global.add.v4.f32 [%0], {%1,%2,%3,%4};"
                 :: "l"(p), "f"(x), "f"(y), "f"(z), "f"(w) : "memory");
}

__device__ __forceinline__ int wscan_incl(int v, int lane) {
#pragma unroll
    for (int d = 1; d < 32; d <<= 1) {
        int t = __shfl_up_sync(0xffffffffu, v, d);
        if (lane >= d) v += t;
    }
    return v;
}

// zero div16, scr, deg, w
__global__ void k_pre() {
    int t = blockIdx.x * blockDim.x + threadIdx.x;
    if (t < NN * CIN) g_div16[t] = 0.f;
    if (t < 6 * C) g_scr[t] = 0.f;
    if (t < NN) { g_deg[t] = 0; g_w[t] = 0; }
}

__global__ void k_deg(const int* __restrict__ iInd, const int* __restrict__ jInd) {
    int e = blockIdx.x * blockDim.x + threadIdx.x;
    if (e >= NE) return;
    int i = iInd[e], j = jInd[e];
    atomicAdd(&g_deg[i], 1);
    atomicAdd(&g_deg[j], 1);
    atomicAdd(&g_w[i], 1);
    atomicAdd(&g_w[j], -1);
}

// scan phase 1: per-block sums of deg
__global__ void k_bsum() {
    int idx = blockIdx.x * 256 + threadIdx.x;
    int v = (idx < NN) ? g_deg[idx] : 0;
    int lane = threadIdx.x & 31, w = threadIdx.x >> 5;
#pragma unroll
    for (int d = 16; d > 0; d >>= 1) v += __shfl_down_sync(0xffffffffu, v, d);
    __shared__ int ws[8];
    if (lane == 0) ws[w] = v;
    __syncthreads();
    if (threadIdx.x == 0) {
        int s = 0;
#pragma unroll
        for (int k = 0; k < 8; k++) s += ws[k];
        g_bsum[blockIdx.x] = s;
    }
}

// scan phase 2: exclusive scan of block sums (1 block, 256 threads >= NBLK)
__global__ void k_bscan() {
    int t = threadIdx.x;
    int v = (t < NBLK) ? g_bsum[t] : 0;
    int lane = t & 31, w = t >> 5;
    int incl = wscan_incl(v, lane);
    __shared__ int ws[8];
    if (lane == 31) ws[w] = incl;
    __syncthreads();
    if (w == 0 && lane < 8) {
        int x = ws[lane];
#pragma unroll
        for (int d = 1; d < 8; d <<= 1) {
            int tt = __shfl_up_sync(0x000000ffu, x, d);
            if (lane >= d) x += tt;
        }
        ws[lane] = x;
    }
    __syncthreads();
    int pref = (w > 0) ? ws[w - 1] : 0;
    if (t < NBLK) g_boff[t] = pref + incl - v;
    if (t == 0) g_off[NN] = 2 * NE;
}

// scan phase 3: per-element exclusive scan within block + block offset
__global__ void k_scan3() {
    int idx = blockIdx.x * 256 + threadIdx.x;
    int v = (idx < NN) ? g_deg[idx] : 0;
    int lane = threadIdx.x & 31, w = threadIdx.x >> 5;
    int incl = wscan_incl(v, lane);
    __shared__ int ws[8];
    if (lane == 31) ws[w] = incl;
    __syncthreads();
    if (w == 0 && lane < 8) {
        int x = ws[lane];
#pragma unroll
        for (int d = 1; d < 8; d <<= 1) {
            int tt = __shfl_up_sync(0x000000ffu, x, d);
            if (lane >= d) x += tt;
        }
        ws[lane] = x;
    }
    __syncthreads();
    int pref = (w > 0) ? ws[w - 1] : 0;
    if (idx < NN) {
        int o = g_boff[blockIdx.x] + pref + incl - v;
        g_off[idx] = o;
        g_cur[idx] = o;
    }
}

__global__ void k_fill(const int* __restrict__ iInd, const int* __restrict__ jInd) {
    int e = blockIdx.x * blockDim.x + threadIdx.x;
    if (e >= NE) return;
    int i = iInd[e], j = jInd[e];
    int p = atomicAdd(&g_cur[i], 1);
    g_adj[p] = (j << 1);
    int q = atomicAdd(&g_cur[j], 1);
    g_adj[q] = (i << 1) | 1;
}

// M2 = KEclose @ KEopen (16x16)
__global__ void k_m2(const float* __restrict__ KEc, const float* __restrict__ KEo) {
    int t = threadIdx.x;
    int co = t >> 4, ci = t & 15;
    float s = 0.f;
#pragma unroll
    for (int k = 0; k < C; k++) s += KEc[co * C + k] * KEo[k * CIN + ci];
    g_M2[co * CIN + ci] = s;
}

// node open: out[n][k] = sum_c K[k*CIN+c] * in[c*count+n]
__global__ void k_open(const float* __restrict__ in, const float* __restrict__ K,
                       float* __restrict__ out, int count) {
    __shared__ __align__(16) float KT[CIN * C];
    for (int idx = threadIdx.x; idx < CIN * C; idx += blockDim.x) {
        int k = idx & (C - 1); int c = idx >> 6;
        KT[idx] = K[k * CIN + c];
    }
    __syncthreads();
    int n = blockIdx.x * blockDim.x + threadIdx.x;
    if (n >= count) return;
    float4 acc[C / 4];
#pragma unroll
    for (int q = 0; q < C / 4; q++) acc[q] = make_float4(0.f, 0.f, 0.f, 0.f);
#pragma unroll
    for (int c = 0; c < CIN; c++) {
        float v = __ldg(&in[(size_t)c * count + n]);
        const float4* w = (const float4*)&KT[c * C];
#pragma unroll
        for (int q = 0; q < C / 4; q++) {
            float4 t = w[q];
            acc[q].x += t.x * v; acc[q].y += t.y * v;
            acc[q].z += t.z * v; acc[q].w += t.w * v;
        }
    }
    float4* o = (float4*)&out[(size_t)n * C];
#pragma unroll
    for (int q = 0; q < C / 4; q++) o[q] = acc[q];
}

// scatter raw xe into g_div16
__global__ void k_edge0(const float* __restrict__ xe, const int* __restrict__ iInd,
                        const int* __restrict__ jInd) {
    int e = blockIdx.x * blockDim.x + threadIdx.x;
    if (e >= NE) return;
    int i = __ldg(&iInd[e]);
    int j = __ldg(&jInd[e]);
    float a[CIN];
#pragma unroll
    for (int c = 0; c < CIN; c++) a[c] = __ldg(&xe[(size_t)c * NE + e]);
    float* di = &g_div16[(size_t)i * CIN];
    float* dj = &g_div16[(size_t)j * CIN];
#pragma unroll
    for (int k = 0; k < 4; k++)
        red4(di + k * 4, a[k * 4], a[k * 4 + 1], a[k * 4 + 2], a[k * 4 + 3]);
#pragma unroll
    for (int k = 0; k < 4; k++)
        red4(dj + k * 4, -a[k * 4], -a[k * 4 + 1], -a[k * 4 + 2], -a[k * 4 + 3]);
}

// expand: g_div = KEopen @ g_div16
__global__ void k_expand(const float* __restrict__ KEo) {
    __shared__ __align__(16) float KT[CIN * C];
    for (int idx = threadIdx.x; idx < CIN * C; idx += blockDim.x) {
        int k = idx & (C - 1); int c = idx >> 6;
        KT[idx] = KEo[k * CIN + c];
    }
    __syncthreads();
    int n = blockIdx.x * blockDim.x + threadIdx.x;
    if (n >= NN) return;
    float d[CIN];
#pragma unroll
    for (int k = 0; k < 4; k++)
        *(float4*)&d[k * 4] = *(const float4*)&g_div16[(size_t)n * CIN + k * 4];
    float4 acc[C / 4];
#pragma unroll
    for (int q = 0; q < C / 4; q++) acc[q] = make_float4(0.f, 0.f, 0.f, 0.f);
#pragma unroll
    for (int c = 0; c < CIN; c++) {
        float v = d[c];
        const float4* w = (const float4*)&KT[c * C];
#pragma unroll
        for (int q = 0; q < C / 4; q++) {
            float4 t = w[q];
            acc[q].x += t.x * v; acc[q].y += t.y * v;
            acc[q].z += t.z * v; acc[q].w += t.w * v;
        }
    }
    float4* o = (float4*)&g_div[(size_t)n * C];
#pragma unroll
    for (int q = 0; q < C / 4; q++) o[q] = acc[q];
}

// matmul: 2 nodes x 16 outputs per thread, padded conflict-free layout
__global__ void k_mmv3(const float* __restrict__ In, const float* __restrict__ M,
                       float* __restrict__ Out, int count) {
    __shared__ __align__(16) float MT[C * 80];
    for (int idx = threadIdx.x; idx < C * C; idx += 256) {
        int k = idx & (C - 1); int c = idx >> 6;
        MT[c * 80 + (k >> 4) * 20 + (k & 15)] = M[k * C + c];
    }
    __syncthreads();
    int t = blockIdx.x * 256 + threadIdx.x;
    int p = t >> 2;
    int q = t & 3;
    int n0 = p * 2;
    if (n0 >= count) return;
    const float4* r0 = (const float4*)&In[(size_t)n0 * C];
    const float4* r1 = (const float4*)&In[(size_t)(n0 + 1) * C];
    float4 b0 = make_float4(0.f, 0.f, 0.f, 0.f), b1 = b0, b2 = b0, b3 = b0;
    float4 d0 = b0, d1 = b0, d2 = b0, d3 = b0;
#pragma unroll
    for (int c4 = 0; c4 < 16; c4++) {
        float4 u = __ldg(&r0[c4]);
        float4 v = __ldg(&r1[c4]);
#pragma unroll
        for (int cc = 0; cc < 4; cc++) {
            float su = (cc == 0) ? u.x : (cc == 1) ? u.y : (cc == 2) ? u.z : u.w;
            float sv = (cc == 0) ? v.x : (cc == 1) ? v.y : (cc == 2) ? v.z : v.w;
            const float4* w = (const float4*)&MT[(c4 * 4 + cc) * 80 + q * 20];
            float4 w0 = w[0], w1 = w[1], w2 = w[2], w3 = w[3];
            b0.x += w0.x * su; b0.y += w0.y * su; b0.z += w0.z * su; b0.w += w0.w * su;
            b1.x += w1.x * su; b1.y += w1.y * su; b1.z += w1.z * su; b1.w += w1.w * su;
            b2.x += w2.x * su; b2.y += w2.y * su; b2.z += w2.z * su; b2.w += w2.w * su;
            b3.x += w3.x * su; b3.y += w3.y * su; b3.z += w3.z * su; b3.w += w3.w * su;
            d0.x += w0.x * sv; d0.y += w0.y * sv; d0.z += w0.z * sv; d0.w += w0.w * sv;
            d1.x += w1.x * sv; d1.y += w1.y * sv; d1.z += w1.z * sv; d1.w += w1.w * sv;
            d2.x += w2.x * sv; d2.y += w2.y * sv; d2.z += w2.z * sv; d2.w += w2.w * sv;
            d3.x += w3.x * sv; d3.y += w3.y * sv; d3.z += w3.z * sv; d3.w += w3.w * sv;
        }
    }
    float4* o0 = (float4*)&Out[(size_t)n0 * C + q * 16];
    o0[0] = b0; o0[1] = b1; o0[2] = b2; o0[3] = b3;
    float4* o1 = (float4*)&Out[(size_t)(n0 + 1) * C + q * 16];
    o1[0] = d0; o1[1] = d1; o1[2] = d2; o1[3] = d3;
}

// per-channel sum & sumsq of X[count][64] into g_scr[off..off+2C)
__global__ void k_stats(const float* __restrict__ X, int count, int off) {
    int t = blockIdx.x * blockDim.x + threadIdx.x;
    int c = t & (C - 1);
    int row0 = t >> 6;
    int nrows = (gridDim.x * blockDim.x) >> 6;
    float s = 0.f, q = 0.f;
    for (int n = row0; n < count; n += nrows) {
        float v = __ldg(&X[(size_t)n * C + c]);
        s += v; q += v * v;
    }
    __shared__ float ss[C], sq[C];
    if (threadIdx.x < C) { ss[threadIdx.x] = 0.f; sq[threadIdx.x] = 0.f; }
    __syncthreads();
    atomicAdd(&ss[c], s);
    atomicAdd(&sq[c], q);
    __syncthreads();
    if (threadIdx.x < C) {
        atomicAdd(&g_scr[off + threadIdx.x], ss[threadIdx.x]);
        atomicAdd(&g_scr[off + C + threadIdx.x], sq[threadIdx.x]);
    }
}

// CSR stats for A-norm, 32 threads/node (2 subs per quad-lane, even/odd incidences):
// sum_e y = sum_n w[n] Z[n]; sum_e y^2 = sum_n deg[n] Z[n]^2 - 2 sum_n Z[n].T[n]
__global__ void k_statsZ(const float* __restrict__ Z) {
    __shared__ float ss[C], sq[C];
    if (threadIdx.x < C) { ss[threadIdx.x] = 0.f; sq[threadIdx.x] = 0.f; }
    __syncthreads();
    int t = blockIdx.x * 256 + threadIdx.x;
    int n = t >> 5;
    int sub = (t >> 4) & 1;
    int L = t & 15;
    if (n < NN) {
        float4 zn = *(const float4*)&Z[(size_t)n * C + L * 4];
        float4 T = make_float4(0.f, 0.f, 0.f, 0.f);
        int k1 = g_off[n + 1];
#pragma unroll 2
        for (int k = g_off[n] + sub; k < k1; k += 2) {
            int a = g_adj[k];
            if (!(a & 1)) {
                const float4 zm = __ldg((const float4*)&Z[(size_t)(a >> 1) * C + L * 4]);
                T.x += zm.x; T.y += zm.y; T.z += zm.z; T.w += zm.w;
            }
        }
        float4 s4, q4;
        q4.x = -2.f * zn.x * T.x;
        q4.y = -2.f * zn.y * T.y;
        q4.z = -2.f * zn.z * T.z;
        q4.w = -2.f * zn.w * T.w;
        if (sub == 0) {
            float wf = (float)g_w[n];
            float df = (float)g_deg[n];
            s4.x = wf * zn.x; s4.y = wf * zn.y; s4.z = wf * zn.z; s4.w = wf * zn.w;
            q4.x += df * zn.x * zn.x;
            q4.y += df * zn.y * zn.y;
            q4.z += df * zn.z * zn.z;
            q4.w += df * zn.w * zn.w;
        } else {
            s4 = make_float4(0.f, 0.f, 0.f, 0.f);
        }
        int ch = L * 4;
        if (sub == 0) {
            atomicAdd(&ss[ch + 0], s4.x); atomicAdd(&ss[ch + 1], s4.y);
            atomicAdd(&ss[ch + 2], s4.z); atomicAdd(&ss[ch + 3], s4.w);
        }
        atomicAdd(&sq[ch + 0], q4.x); atomicAdd(&sq[ch + 1], q4.y);
        atomicAdd(&sq[ch + 2], q4.z); atomicAdd(&sq[ch + 3], q4.w);
    }
    __syncthreads();
    if (threadIdx.x < C) {
        atomicAdd(&g_scr[threadIdx.x], ss[threadIdx.x]);
        atomicAdd(&g_scr[C + threadIdx.x], sq[threadIdx.x]);
    }
}

// scales0: A-norm folded -> g_nrmA[l]; W-norm -> g_nrm[2C..4C); zero scr[0,4C)
__global__ void k_scales0(int l) {
    int c = threadIdx.x;
    if (c < C) {
        float s = g_scr[c], q = g_scr[C + c];
        float m = s / (float)NE;
        float rH = HSTEP / sqrtf(fmaxf(q - s * m, 0.f) + EPSV);
        g_nrmA[l * 2 * C + c] = m * rH;
        g_nrmA[l * 2 * C + C + c] = rH;
        s = g_scr[2 * C + c]; q = g_scr[3 * C + c];
        m = s / (float)NN;
        g_nrm[2 * C + c] = m;
        g_nrm[3 * C + c] = 1.f / sqrtf(fmaxf(q - s * m, 0.f) + EPSV);
    }
    __syncthreads();
    g_scr[c] = 0.f;
}

__global__ void k_scales1() {
    int c = threadIdx.x;
    if (c < C) {
        float s = g_scr[4 * C + c], q = g_scr[5 * C + c];
        float m = s / (float)NN;
        g_nrm[4 * C + c] = m;
        g_nrm[5 * C + c] = 1.f / sqrtf(fmaxf(q - s * m, 0.f) + EPSV);
    }
    __syncthreads();
    if (c < 2 * C) g_scr[4 * C + c] = 0.f;
}

// CSR divergence, 32 threads/node, branch-free: contr = s*relu(s*(zn-zm)*r - m)
__global__ void k_divCSR(const float* __restrict__ Z, int l) {
    __shared__ __align__(16) float sm[2 * C];
    if (threadIdx.x < 2 * C) sm[threadIdx.x] = g_nrmA[l * 2 * C + threadIdx.x];
    __syncthreads();
    int t = blockIdx.x * 256 + threadIdx.x;
    int n = t >> 5;
    int sub = (t >> 4) & 1;
    int L = t & 15;
    if (n >= NN) return;
    float4 zn = *(const float4*)&Z[(size_t)n * C + L * 4];
    float4 mm = *(const float4*)&sm[L * 4];
    float4 rr = *(const float4*)&sm[C + L * 4];
    float4 acc = make_float4(0.f, 0.f, 0.f, 0.f);
    int k1 = g_off[n + 1];
#pragma unroll 2
    for (int k = g_off[n] + sub; k < k1; k += 2) {
        int a = g_adj[k];
        float s = (a & 1) ? -1.f : 1.f;
        const float4 zm = __ldg((const float4*)&Z[(size_t)(a >> 1) * C + L * 4]);
        acc.x += s * fmaxf(s * (zn.x - zm.x) * rr.x - mm.x, 0.f);
        acc.y += s * fmaxf(s * (zn.y - zm.y) * rr.y - mm.y, 0.f);
        acc.z += s * fmaxf(s * (zn.z - zm.z) * rr.z - mm.z, 0.f);
        acc.w += s * fmaxf(s * (zn.w - zm.w) * rr.w - mm.w, 0.f);
    }
    // combine the two sub-halves (lanes differ by 16 within the warp)
    acc.x += __shfl_xor_sync(0xffffffffu, acc.x, 16);
    acc.y += __shfl_xor_sync(0xffffffffu, acc.y, 16);
    acc.z += __shfl_xor_sync(0xffffffffu, acc.z, 16);
    acc.w += __shfl_xor_sync(0xffffffffu, acc.w, 16);
    if (sub == 0) {
        float4* dv = (float4*)&g_div[(size_t)n * C + L * 4];
        float4 d = *dv;
        d.x += acc.x; d.y += acc.y; d.z += acc.z; d.w += acc.w;
        *dv = d;
    }
}

// xn -= H * (relu(norm(U)) + relu(norm(W)))
__global__ void k_update() {
    __shared__ __align__(16) float sm[4 * C];
    if (threadIdx.x < 4 * C) sm[threadIdx.x] = g_nrm[2 * C + threadIdx.x];
    __syncthreads();
    int n = blockIdx.x * blockDim.x + threadIdx.x;
    if (n >= NN) return;
#pragma unroll
    for (int q = 0; q < 16; q++) {
        float4 u = *(const float4*)&g_U[(size_t)n * C + q * 4];
        float4 w = *(const float4*)&g_W[(size_t)n * C + q * 4];
        float4 x = *(float4*)&g_Xn[(size_t)n * C + q * 4];
        float4 mw = *(const float4*)&sm[q * 4];
        float4 rw = *(const float4*)&sm[C + q * 4];
        float4 mu = *(const float4*)&sm[2 * C + q * 4];
        float4 ru = *(const float4*)&sm[3 * C + q * 4];
        x.x -= HSTEP * (fmaxf((u.x - mu.x) * ru.x, 0.f) + fmaxf((w.x - mw.x) * rw.x, 0.f));
        x.y -= HSTEP * (fmaxf((u.y - mu.y) * ru.y, 0.f) + fmaxf((w.y - mw.y) * rw.y, 0.f));
        x.z -= HSTEP * (fmaxf((u.z - mu.z) * ru.z, 0.f) + fmaxf((w.z - mw.z) * rw.z, 0.f));
        x.w -= HSTEP * (fmaxf((u.w - mu.w) * ru.w, 0.f) + fmaxf((w.w - mw.w) * rw.w, 0.f));
        *(float4*)&g_Xn[(size_t)n * C + q * 4] = x;
    }
}

// node close
__global__ void k_close(const float* __restrict__ Kc, const float* __restrict__ In,
                        float* __restrict__ out, int count) {
    __shared__ __align__(16) float Ks[CIN * C];
    for (int idx = threadIdx.x; idx < CIN * C; idx += blockDim.x) Ks[idx] = Kc[idx];
    __syncthreads();
    int n = blockIdx.x * blockDim.x + threadIdx.x;
    if (n >= count) return;
    float4 row[16];
#pragma unroll
    for (int q = 0; q < 16; q++)
        row[q] = __ldg((const float4*)&In[(size_t)n * C + q * 4]);
#pragma unroll
    for (int co = 0; co < CIN; co++) {
        float acc = 0.f;
#pragma unroll
        for (int q = 0; q < 16; q++) {
            float4 w = *(const float4*)&Ks[co * C + q * 4];
            acc += w.x * row[q].x + w.y * row[q].y + w.z * row[q].z + w.w * row[q].w;
        }
        out[(size_t)co * count + n] = acc;
    }
}

// edge mega-close
__global__ void k_closeMega(const float* __restrict__ xe, const float* __restrict__ KEclose,
                            const int* __restrict__ iInd, const int* __restrict__ jInd,
                            float* __restrict__ out) {
    __shared__ __align__(16) float KEc[CIN * C];
    __shared__ __align__(16) float smA[NL * 2 * C];
    __shared__ float M2s[CIN * CIN];
    int tx = threadIdx.x;
    for (int idx = tx; idx < CIN * C; idx += 256) KEc[idx] = KEclose[idx];
    for (int idx = tx; idx < NL * 2 * C; idx += 256) smA[idx] = g_nrmA[idx];
    if (tx < CIN * CIN) M2s[tx] = g_M2[tx];
    __syncthreads();
    int t = blockIdx.x * 256 + tx;
    int e = t >> 4;
    int L = t & 15;
    int wl = tx & 31;
    int i = __ldg(&iInd[e]);
    int j = __ldg(&jInd[e]);
    float4 vs = make_float4(0.f, 0.f, 0.f, 0.f);
#pragma unroll
    for (int l = 0; l < NL; l++) {
        const float* Z = &g_Zs[(size_t)l * NN * C];
        float4 a = __ldg((const float4*)&Z[(size_t)i * C + L * 4]);
        float4 b = __ldg((const float4*)&Z[(size_t)j * C + L * 4]);
        float4 m = *(const float4*)&smA[l * 2 * C + L * 4];
        float4 r = *(const float4*)&smA[l * 2 * C + C + L * 4];
        vs.x += fmaxf((a.x - b.x) * r.x - m.x, 0.f);
        vs.y += fmaxf((a.y - b.y) * r.y - m.y, 0.f);
        vs.z += fmaxf((a.z - b.z) * r.z - m.z, 0.f);
        vs.w += fmaxf((a.w - b.w) * r.w - m.w, 0.f);
    }
    float pr[16];
#pragma unroll
    for (int co = 0; co < CIN; co++) {
        const float4 w = *(const float4*)&KEc[co * C + L * 4];
        pr[co] = w.x * vs.x + w.y * vs.y + w.z * vs.z + w.w * vs.w;
    }
#pragma unroll
    for (int d = 1; d < 16; d <<= 1) {
#pragma unroll
        for (int co = 0; co < CIN; co++)
            pr[co] += __shfl_xor_sync(0xffffffffu, pr[co], d);
    }
    float xr = __ldg(&xe[(size_t)L * NE + e]);
    float acc = pr[L];
    int half = wl & 16;
#pragma unroll
    for (int c = 0; c < CIN; c++) {
        float xc = __shfl_sync(0xffffffffu, xr, half + c);
        acc += M2s[L * CIN + c] * xc;
    }
    out[(size_t)L * NE + e] = acc;
}

extern "C" void kernel_launch(void* const* d_in, const int* in_sizes, int n_in,
                              void* d_out, int out_size) {
    const float* xn      = (const float*)d_in[0];
    const float* xe      = (const float*)d_in[1];
    const int*   iInd    = (const int*)d_in[2];
    const int*   jInd    = (const int*)d_in[3];
    const float* KNopen  = (const float*)d_in[4];
    const float* KEopen  = (const float*)d_in[5];
    const float* KNclose = (const float*)d_in[6];
    const float* KEclose = (const float*)d_in[7];
    const float* KN      = (const float*)d_in[8];
    const float* KE      = (const float*)d_in[9];
    const float* KD      = (const float*)d_in[10];
    float* out = (float*)d_out;
    (void)in_sizes; (void)n_in; (void)out_size;

    float *pXn, *pZs, *pW, *pU, *pDiv;
    cudaGetSymbolAddress((void**)&pXn, g_Xn);
    cudaGetSymbolAddress((void**)&pZs, g_Zs);
    cudaGetSymbolAddress((void**)&pW, g_W);
    cudaGetSymbolAddress((void**)&pU, g_U);
    cudaGetSymbolAddress((void**)&pDiv, g_div);

    const int TB = 256;
    const int gN = (NN + TB - 1) / TB;          // 196
    const int gE = (NE + TB - 1) / TB;          // 3125
    const int gMM = (NN * 2 + TB - 1) / TB;     // 391
    const int gCSR = (NN * 32 + TB - 1) / TB;   // 6250
    const int gEB = (NE * 16) / TB;             // 50000

    k_pre<<<gE, TB>>>();
    k_m2<<<1, TB>>>(KEclose, KEopen);
    k_deg<<<gE, TB>>>(iInd, jInd);
    k_bsum<<<NBLK, TB>>>();
    k_bscan<<<1, TB>>>();
    k_scan3<<<NBLK, TB>>>();
    k_fill<<<gE, TB>>>(iInd, jInd);
    k_open<<<gN, TB>>>(xn, KNopen, pXn, NN);
    k_edge0<<<gE, TB>>>(xe, iInd, jInd);
    k_expand<<<gN, TB>>>(KEopen);

    for (int l = 0; l < NL; l++) {
        const float* Kn = KN + (size_t)l * C * C;
        const float* Ke = KE + (size_t)l * C * C;
        const float* Kd = KD + (size_t)l * C * C;
        float* pZ = pZs + (size_t)l * NN * C;

        k_mmv3<<<gMM, TB>>>(pXn, Kn, pZ, NN);
        k_mmv3<<<gMM, TB>>>(pXn, Kd, pW, NN);
        k_stats<<<256, TB>>>(pW, NN, 2 * C);
        k_statsZ<<<gCSR, TB>>>(pZ);
        k_scales0<<<1, TB>>>(l);
        k_divCSR<<<gCSR, TB>>>(pZ, l);
        k_mmv3<<<gMM, TB>>>(pDiv, Ke, pU, NN);
        k_stats<<<256, TB>>>(pU, NN, 4 * C);
        k_scales1<<<1, TB>>>();
        k_update<<<gN, TB>>>();
    }

    k_close<<<gN, TB>>>(KNclose, pXn, out, NN);
    k_closeMega<<<gEB, TB>>>(xe, KEclose, iInd, jInd, out + (size_t)CIN * NN);
}

// round 16
// speedup vs baseline: 1.0444x; 1.0444x over previous
#include <cuda_runtime.h>
#include <cuda_fp16.h>

#define NN 50000
#define NE 800000
#define C 64
#define CIN 16
#define NL 4
#define HSTEP 0.1f
#define EPSV 1e-3f

// ---- static device scratch ----
__device__ __align__(256) float g_Xn[NN * C];
__device__ __align__(256) float g_Zs[(size_t)NL * NN * C];   // per-layer Z (fp32)
__device__ __align__(256) __half2 g_Zh[(size_t)NL * NN * 32]; // fp16 mirror of Z
__device__ __align__(256) float g_W[NN * C];
__device__ __align__(256) float g_U[NN * C];
__device__ __align__(256) float g_div[NN * C];
__device__ __align__(256) float g_div16[NN * CIN];
__device__ __align__(256) float g_scr[6 * C];
__device__ __align__(256) float g_nrm[6 * C];
__device__ __align__(256) float g_nrmA[NL * 2 * C];
__device__ __align__(256) float g_M2[CIN * CIN];
// CSR
#define NBLK ((NN + 255) / 256)   // 196
__device__ int g_deg[NN];
__device__ int g_w[NN];
__device__ int g_off[NN + 1];
__device__ int g_cur[NN];
__device__ int g_adj[2 * NE];
__device__ int g_bsum[NBLK];
__device__ int g_boff[NBLK];

__device__ __forceinline__ void red4(float* p, float x, float y, float z, float w) {
    asm volatile("red.global.add.v4.f32 [%0], {%1,%2,%3,%4};"
                 :: "l"(p), "f"(x), "f"(y), "f"(z), "f"(w) : "memory");
}

__device__ __forceinline__ int wscan_incl(int v, int lane) {
#pragma unroll
    for (int d = 1; d < 32; d <<= 1) {
        int t = __shfl_up_sync(0xffffffffu, v, d);
        if (lane >= d) v += t;
    }
    return v;
}

// load 4 channels (lane L) from fp16 Z mirror
__device__ __forceinline__ float4 ldZh(const __half2* Zh, size_t node, int L) {
    uint2 raw = __ldg((const uint2*)(Zh + node * 32 + L * 2));
    __half2 h0 = *(__half2*)&raw.x;
    __half2 h1 = *(__half2*)&raw.y;
    float2 f0 = __half22float2(h0);
    float2 f1 = __half22float2(h1);
    return make_float4(f0.x, f0.y, f1.x, f1.y);
}

// zero div16, scr, deg, w
__global__ void k_pre() {
    int t = blockIdx.x * blockDim.x + threadIdx.x;
    if (t < NN * CIN) g_div16[t] = 0.f;
    if (t < 6 * C) g_scr[t] = 0.f;
    if (t < NN) { g_deg[t] = 0; g_w[t] = 0; }
}

__global__ void k_deg(const int* __restrict__ iInd, const int* __restrict__ jInd) {
    int e = blockIdx.x * blockDim.x + threadIdx.x;
    if (e >= NE) return;
    int i = iInd[e], j = jInd[e];
    atomicAdd(&g_deg[i], 1);
    atomicAdd(&g_deg[j], 1);
    atomicAdd(&g_w[i], 1);
    atomicAdd(&g_w[j], -1);
}

__global__ void k_bsum() {
    int idx = blockIdx.x * 256 + threadIdx.x;
    int v = (idx < NN) ? g_deg[idx] : 0;
    int lane = threadIdx.x & 31, w = threadIdx.x >> 5;
#pragma unroll
    for (int d = 16; d > 0; d >>= 1) v += __shfl_down_sync(0xffffffffu, v, d);
    __shared__ int ws[8];
    if (lane == 0) ws[w] = v;
    __syncthreads();
    if (threadIdx.x == 0) {
        int s = 0;
#pragma unroll
        for (int k = 0; k < 8; k++) s += ws[k];
        g_bsum[blockIdx.x] = s;
    }
}

__global__ void k_bscan() {
    int t = threadIdx.x;
    int v = (t < NBLK) ? g_bsum[t] : 0;
    int lane = t & 31, w = t >> 5;
    int incl = wscan_incl(v, lane);
    __shared__ int ws[8];
    if (lane == 31) ws[w] = incl;
    __syncthreads();
    if (w == 0 && lane < 8) {
        int x = ws[lane];
#pragma unroll
        for (int d = 1; d < 8; d <<= 1) {
            int tt = __shfl_up_sync(0x000000ffu, x, d);
            if (lane >= d) x += tt;
        }
        ws[lane] = x;
    }
    __syncthreads();
    int pref = (w > 0) ? ws[w - 1] : 0;
    if (t < NBLK) g_boff[t] = pref + incl - v;
    if (t == 0) g_off[NN] = 2 * NE;
}

__global__ void k_scan3() {
    int idx = blockIdx.x * 256 + threadIdx.x;
    int v = (idx < NN) ? g_deg[idx] : 0;
    int lane = threadIdx.x & 31, w = threadIdx.x >> 5;
    int incl = wscan_incl(v, lane);
    __shared__ int ws[8];
    if (lane == 31) ws[w] = incl;
    __syncthreads();
    if (w == 0 && lane < 8) {
        int x = ws[lane];
#pragma unroll
        for (int d = 1; d < 8; d <<= 1) {
            int tt = __shfl_up_sync(0x000000ffu, x, d);
            if (lane >= d) x += tt;
        }
        ws[lane] = x;
    }
    __syncthreads();
    int pref = (w > 0) ? ws[w - 1] : 0;
    if (idx < NN) {
        int o = g_boff[blockIdx.x] + pref + incl - v;
        g_off[idx] = o;
        g_cur[idx] = o;
    }
}

__global__ void k_fill(const int* __restrict__ iInd, const int* __restrict__ jInd) {
    int e = blockIdx.x * blockDim.x + threadIdx.x;
    if (e >= NE) return;
    int i = iInd[e], j = jInd[e];
    int p = atomicAdd(&g_cur[i], 1);
    g_adj[p] = (j << 1);
    int q = atomicAdd(&g_cur[j], 1);
    g_adj[q] = (i << 1) | 1;
}

__global__ void k_m2(const float* __restrict__ KEc, const float* __restrict__ KEo) {
    int t = threadIdx.x;
    int co = t >> 4, ci = t & 15;
    float s = 0.f;
#pragma unroll
    for (int k = 0; k < C; k++) s += KEc[co * C + k] * KEo[k * CIN + ci];
    g_M2[co * CIN + ci] = s;
}

__global__ void k_open(const float* __restrict__ in, const float* __restrict__ K,
                       float* __restrict__ out, int count) {
    __shared__ __align__(16) float KT[CIN * C];
    for (int idx = threadIdx.x; idx < CIN * C; idx += blockDim.x) {
        int k = idx & (C - 1); int c = idx >> 6;
        KT[idx] = K[k * CIN + c];
    }
    __syncthreads();
    int n = blockIdx.x * blockDim.x + threadIdx.x;
    if (n >= count) return;
    float4 acc[C / 4];
#pragma unroll
    for (int q = 0; q < C / 4; q++) acc[q] = make_float4(0.f, 0.f, 0.f, 0.f);
#pragma unroll
    for (int c = 0; c < CIN; c++) {
        float v = __ldg(&in[(size_t)c * count + n]);
        const float4* w = (const float4*)&KT[c * C];
#pragma unroll
        for (int q = 0; q < C / 4; q++) {
            float4 t = w[q];
            acc[q].x += t.x * v; acc[q].y += t.y * v;
            acc[q].z += t.z * v; acc[q].w += t.w * v;
        }
    }
    float4* o = (float4*)&out[(size_t)n * C];
#pragma unroll
    for (int q = 0; q < C / 4; q++) o[q] = acc[q];
}

__global__ void k_edge0(const float* __restrict__ xe, const int* __restrict__ iInd,
                        const int* __restrict__ jInd) {
    int e = blockIdx.x * blockDim.x + threadIdx.x;
    if (e >= NE) return;
    int i = __ldg(&iInd[e]);
    int j = __ldg(&jInd[e]);
    float a[CIN];
#pragma unroll
    for (int c = 0; c < CIN; c++) a[c] = __ldg(&xe[(size_t)c * NE + e]);
    float* di = &g_div16[(size_t)i * CIN];
    float* dj = &g_div16[(size_t)j * CIN];
#pragma unroll
    for (int k = 0; k < 4; k++)
        red4(di + k * 4, a[k * 4], a[k * 4 + 1], a[k * 4 + 2], a[k * 4 + 3]);
#pragma unroll
    for (int k = 0; k < 4; k++)
        red4(dj + k * 4, -a[k * 4], -a[k * 4 + 1], -a[k * 4 + 2], -a[k * 4 + 3]);
}

__global__ void k_expand(const float* __restrict__ KEo) {
    __shared__ __align__(16) float KT[CIN * C];
    for (int idx = threadIdx.x; idx < CIN * C; idx += blockDim.x) {
        int k = idx & (C - 1); int c = idx >> 6;
        KT[idx] = KEo[k * CIN + c];
    }
    __syncthreads();
    int n = blockIdx.x * blockDim.x + threadIdx.x;
    if (n >= NN) return;
    float d[CIN];
#pragma unroll
    for (int k = 0; k < 4; k++)
        *(float4*)&d[k * 4] = *(const float4*)&g_div16[(size_t)n * CIN + k * 4];
    float4 acc[C / 4];
#pragma unroll
    for (int q = 0; q < C / 4; q++) acc[q] = make_float4(0.f, 0.f, 0.f, 0.f);
#pragma unroll
    for (int c = 0; c < CIN; c++) {
        float v = d[c];
        const float4* w = (const float4*)&KT[c * C];
#pragma unroll
        for (int q = 0; q < C / 4; q++) {
            float4 t = w[q];
            acc[q].x += t.x * v; acc[q].y += t.y * v;
            acc[q].z += t.z * v; acc[q].w += t.w * v;
        }
    }
    float4* o = (float4*)&g_div[(size_t)n * C];
#pragma unroll
    for (int q = 0; q < C / 4; q++) o[q] = acc[q];
}

// matmul: 2 nodes x 16 outputs per thread, padded conflict-free layout.
// WH=1: also write fp16 mirror.
template <int WH>
__global__ void k_mmv3(const float* __restrict__ In, const float* __restrict__ M,
                       float* __restrict__ Out, __half2* __restrict__ OutH, int count) {
    __shared__ __align__(16) float MT[C * 80];
    for (int idx = threadIdx.x; idx < C * C; idx += 256) {
        int k = idx & (C - 1); int c = idx >> 6;
        MT[c * 80 + (k >> 4) * 20 + (k & 15)] = M[k * C + c];
    }
    __syncthreads();
    int t = blockIdx.x * 256 + threadIdx.x;
    int p = t >> 2;
    int q = t & 3;
    int n0 = p * 2;
    if (n0 >= count) return;
    const float4* r0 = (const float4*)&In[(size_t)n0 * C];
    const float4* r1 = (const float4*)&In[(size_t)(n0 + 1) * C];
    float4 b0 = make_float4(0.f, 0.f, 0.f, 0.f), b1 = b0, b2 = b0, b3 = b0;
    float4 d0 = b0, d1 = b0, d2 = b0, d3 = b0;
#pragma unroll
    for (int c4 = 0; c4 < 16; c4++) {
        float4 u = __ldg(&r0[c4]);
        float4 v = __ldg(&r1[c4]);
#pragma unroll
        for (int cc = 0; cc < 4; cc++) {
            float su = (cc == 0) ? u.x : (cc == 1) ? u.y : (cc == 2) ? u.z : u.w;
            float sv = (cc == 0) ? v.x : (cc == 1) ? v.y : (cc == 2) ? v.z : v.w;
            const float4* w = (const float4*)&MT[(c4 * 4 + cc) * 80 + q * 20];
            float4 w0 = w[0], w1 = w[1], w2 = w[2], w3 = w[3];
            b0.x += w0.x * su; b0.y += w0.y * su; b0.z += w0.z * su; b0.w += w0.w * su;
            b1.x += w1.x * su; b1.y += w1.y * su; b1.z += w1.z * su; b1.w += w1.w * su;
            b2.x += w2.x * su; b2.y += w2.y * su; b2.z += w2.z * su; b2.w += w2.w * su;
            b3.x += w3.x * su; b3.y += w3.y * su; b3.z += w3.z * su; b3.w += w3.w * su;
            d0.x += w0.x * sv; d0.y += w0.y * sv; d0.z += w0.z * sv; d0.w += w0.w * sv;
            d1.x += w1.x * sv; d1.y += w1.y * sv; d1.z += w1.z * sv; d1.w += w1.w * sv;
            d2.x += w2.x * sv; d2.y += w2.y * sv; d2.z += w2.z * sv; d2.w += w2.w * sv;
            d3.x += w3.x * sv; d3.y += w3.y * sv; d3.z += w3.z * sv; d3.w += w3.w * sv;
        }
    }
    float4* o0 = (float4*)&Out[(size_t)n0 * C + q * 16];
    o0[0] = b0; o0[1] = b1; o0[2] = b2; o0[3] = b3;
    float4* o1 = (float4*)&Out[(size_t)(n0 + 1) * C + q * 16];
    o1[0] = d0; o1[1] = d1; o1[2] = d2; o1[3] = d3;
    if (WH) {
        __align__(16) __half2 h[8];
        h[0] = __floats2half2_rn(b0.x, b0.y); h[1] = __floats2half2_rn(b0.z, b0.w);
        h[2] = __floats2half2_rn(b1.x, b1.y); h[3] = __floats2half2_rn(b1.z, b1.w);
        h[4] = __floats2half2_rn(b2.x, b2.y); h[5] = __floats2half2_rn(b2.z, b2.w);
        h[6] = __floats2half2_rn(b3.x, b3.y); h[7] = __floats2half2_rn(b3.z, b3.w);
        *(uint4*)&OutH[(size_t)n0 * 32 + q * 8] = *(uint4*)h;
        h[0] = __floats2half2_rn(d0.x, d0.y); h[1] = __floats2half2_rn(d0.z, d0.w);
        h[2] = __floats2half2_rn(d1.x, d1.y); h[3] = __floats2half2_rn(d1.z, d1.w);
        h[4] = __floats2half2_rn(d2.x, d2.y); h[5] = __floats2half2_rn(d2.z, d2.w);
        h[6] = __floats2half2_rn(d3.x, d3.y); h[7] = __floats2half2_rn(d3.z, d3.w);
        *(uint4*)&OutH[(size_t)(n0 + 1) * 32 + q * 8] = *(uint4*)h;
    }
}

__global__ void k_stats(const float* __restrict__ X, int count, int off) {
    int t = blockIdx.x * blockDim.x + threadIdx.x;
    int c = t & (C - 1);
    int row0 = t >> 6;
    int nrows = (gridDim.x * blockDim.x) >> 6;
    float s = 0.f, q = 0.f;
    for (int n = row0; n < count; n += nrows) {
        float v = __ldg(&X[(size_t)n * C + c]);
        s += v; q += v * v;
    }
    __shared__ float ss[C], sq[C];
    if (threadIdx.x < C) { ss[threadIdx.x] = 0.f; sq[threadIdx.x] = 0.f; }
    __syncthreads();
    atomicAdd(&ss[c], s);
    atomicAdd(&sq[c], q);
    __syncthreads();
    if (threadIdx.x < C) {
        atomicAdd(&g_scr[off + threadIdx.x], ss[threadIdx.x]);
        atomicAdd(&g_scr[off + C + threadIdx.x], sq[threadIdx.x]);
    }
}

// CSR stats, 16 threads/node; T gathered from fp16 mirror
__global__ void k_statsZ(const float* __restrict__ Z, const __half2* __restrict__ Zh) {
    __shared__ float ss[C], sq[C];
    if (threadIdx.x < C) { ss[threadIdx.x] = 0.f; sq[threadIdx.x] = 0.f; }
    __syncthreads();
    int t = blockIdx.x * 256 + threadIdx.x;
    int n = t >> 4, L = t & 15;
    if (n < NN) {
        float4 zn = *(const float4*)&Z[(size_t)n * C + L * 4];
        float wf = (float)g_w[n];
        float df = (float)g_deg[n];
        float4 T = make_float4(0.f, 0.f, 0.f, 0.f);
        int k1 = g_off[n + 1];
        for (int k = g_off[n]; k < k1; k++) {
            int a = g_adj[k];
            if (!(a & 1)) {
                float4 zm = ldZh(Zh, (size_t)(a >> 1), L);
                T.x += zm.x; T.y += zm.y; T.z += zm.z; T.w += zm.w;
            }
        }
        float4 s4, q4;
        s4.x = wf * zn.x; s4.y = wf * zn.y; s4.z = wf * zn.z; s4.w = wf * zn.w;
        q4.x = df * zn.x * zn.x - 2.f * zn.x * T.x;
        q4.y = df * zn.y * zn.y - 2.f * zn.y * T.y;
        q4.z = df * zn.z * zn.z - 2.f * zn.z * T.z;
        q4.w = df * zn.w * zn.w - 2.f * zn.w * T.w;
        int ch = L * 4;
        atomicAdd(&ss[ch + 0], s4.x); atomicAdd(&ss[ch + 1], s4.y);
        atomicAdd(&ss[ch + 2], s4.z); atomicAdd(&ss[ch + 3], s4.w);
        atomicAdd(&sq[ch + 0], q4.x); atomicAdd(&sq[ch + 1], q4.y);
        atomicAdd(&sq[ch + 2], q4.z); atomicAdd(&sq[ch + 3], q4.w);
    }
    __syncthreads();
    if (threadIdx.x < C) {
        atomicAdd(&g_scr[threadIdx.x], ss[threadIdx.x]);
        atomicAdd(&g_scr[C + threadIdx.x], sq[threadIdx.x]);
    }
}

__global__ void k_scales0(int l) {
    int c = threadIdx.x;
    if (c < C) {
        float s = g_scr[c], q = g_scr[C + c];
        float m = s / (float)NE;
        float rH = HSTEP / sqrtf(fmaxf(q - s * m, 0.f) + EPSV);
        g_nrmA[l * 2 * C + c] = m * rH;
        g_nrmA[l * 2 * C + C + c] = rH;
        s = g_scr[2 * C + c]; q = g_scr[3 * C + c];
        m = s / (float)NN;
        g_nrm[2 * C + c] = m;
        g_nrm[3 * C + c] = 1.f / sqrtf(fmaxf(q - s * m, 0.f) + EPSV);
    }
    __syncthreads();
    g_scr[c] = 0.f;
}

__global__ void k_scales1() {
    int c = threadIdx.x;
    if (c < C) {
        float s = g_scr[4 * C + c], q = g_scr[5 * C + c];
        float m = s / (float)NN;
        g_nrm[4 * C + c] = m;
        g_nrm[5 * C + c] = 1.f / sqrtf(fmaxf(q - s * m, 0.f) + EPSV);
    }
    __syncthreads();
    if (c < 2 * C) g_scr[4 * C + c] = 0.f;
}

// CSR divergence, 16 threads/node, branch-free, fp16 gathers both sides
__global__ void k_divCSR(const __half2* __restrict__ Zh, int l) {
    __shared__ __align__(16) float sm[2 * C];
    if (threadIdx.x < 2 * C) sm[threadIdx.x] = g_nrmA[l * 2 * C + threadIdx.x];
    __syncthreads();
    int t = blockIdx.x * 256 + threadIdx.x;
    int n = t >> 4, L = t & 15;
    if (n >= NN) return;
    float4 zn = ldZh(Zh, (size_t)n, L);
    float4 mm = *(const float4*)&sm[L * 4];
    float4 rr = *(const float4*)&sm[C + L * 4];
    float4 acc = make_float4(0.f, 0.f, 0.f, 0.f);
    int k1 = g_off[n + 1];
    for (int k = g_off[n]; k < k1; k++) {
        int a = g_adj[k];
        float s = (a & 1) ? -1.f : 1.f;
        float4 zm = ldZh(Zh, (size_t)(a >> 1), L);
        acc.x += s * fmaxf(s * (zn.x - zm.x) * rr.x - mm.x, 0.f);
        acc.y += s * fmaxf(s * (zn.y - zm.y) * rr.y - mm.y, 0.f);
        acc.z += s * fmaxf(s * (zn.z - zm.z) * rr.z - mm.z, 0.f);
        acc.w += s * fmaxf(s * (zn.w - zm.w) * rr.w - mm.w, 0.f);
    }
    float4* dv = (float4*)&g_div[(size_t)n * C + L * 4];
    float4 d = *dv;
    d.x += acc.x; d.y += acc.y; d.z += acc.z; d.w += acc.w;
    *dv = d;
}

__global__ void k_update() {
    __shared__ __align__(16) float sm[4 * C];
    if (threadIdx.x < 4 * C) sm[threadIdx.x] = g_nrm[2 * C + threadIdx.x];
    __syncthreads();
    int n = blockIdx.x * blockDim.x + threadIdx.x;
    if (n >= NN) return;
#pragma unroll
    for (int q = 0; q < 16; q++) {
        float4 u = *(const float4*)&g_U[(size_t)n * C + q * 4];
        float4 w = *(const float4*)&g_W[(size_t)n * C + q * 4];
        float4 x = *(float4*)&g_Xn[(size_t)n * C + q * 4];
        float4 mw = *(const float4*)&sm[q * 4];
        float4 rw = *(const float4*)&sm[C + q * 4];
        float4 mu = *(const float4*)&sm[2 * C + q * 4];
        float4 ru = *(const float4*)&sm[3 * C + q * 4];
        x.x -= HSTEP * (fmaxf((u.x - mu.x) * ru.x, 0.f) + fmaxf((w.x - mw.x) * rw.x, 0.f));
        x.y -= HSTEP * (fmaxf((u.y - mu.y) * ru.y, 0.f) + fmaxf((w.y - mw.y) * rw.y, 0.f));
        x.z -= HSTEP * (fmaxf((u.z - mu.z) * ru.z, 0.f) + fmaxf((w.z - mw.z) * rw.z, 0.f));
        x.w -= HSTEP * (fmaxf((u.w - mu.w) * ru.w, 0.f) + fmaxf((w.w - mw.w) * rw.w, 0.f));
        *(float4*)&g_Xn[(size_t)n * C + q * 4] = x;
    }
}

__global__ void k_close(const float* __restrict__ Kc, const float* __restrict__ In,
                        float* __restrict__ out, int count) {
    __shared__ __align__(16) float Ks[CIN * C];
    for (int idx = threadIdx.x; idx < CIN * C; idx += blockDim.x) Ks[idx] = Kc[idx];
    __syncthreads();
    int n = blockIdx.x * blockDim.x + threadIdx.x;
    if (n >= count) return;
    float4 row[16];
#pragma unroll
    for (int q = 0; q < 16; q++)
        row[q] = __ldg((const float4*)&In[(size_t)n * C + q * 4]);
#pragma unroll
    for (int co = 0; co < CIN; co++) {
        float acc = 0.f;
#pragma unroll
        for (int q = 0; q < 16; q++) {
            float4 w = *(const float4*)&Ks[co * C + q * 4];
            acc += w.x * row[q].x + w.y * row[q].y + w.z * row[q].z + w.w * row[q].w;
        }
        out[(size_t)co * count + n] = acc;
    }
}

// edge mega-close, fp16 gathers
__global__ void k_closeMega(const float* __restrict__ xe, const float* __restrict__ KEclose,
                            const int* __restrict__ iInd, const int* __restrict__ jInd,
                            float* __restrict__ out) {
    __shared__ __align__(16) float KEc[CIN * C];
    __shared__ __align__(16) float smA[NL * 2 * C];
    __shared__ float M2s[CIN * CIN];
    int tx = threadIdx.x;
    for (int idx = tx; idx < CIN * C; idx += 256) KEc[idx] = KEclose[idx];
    for (int idx = tx; idx < NL * 2 * C; idx += 256) smA[idx] = g_nrmA[idx];
    if (tx < CIN * CIN) M2s[tx] = g_M2[tx];
    __syncthreads();
    int t = blockIdx.x * 256 + tx;
    int e = t >> 4;
    int L = t & 15;
    int wl = tx & 31;
    int i = __ldg(&iInd[e]);
    int j = __ldg(&jInd[e]);
    float4 vs = make_float4(0.f, 0.f, 0.f, 0.f);
#pragma unroll
    for (int l = 0; l < NL; l++) {
        const __half2* Zh = g_Zh + (size_t)l * NN * 32;
        float4 a = ldZh(Zh, (size_t)i, L);
        float4 b = ldZh(Zh, (size_t)j, L);
        float4 m = *(const float4*)&smA[l * 2 * C + L * 4];
        float4 r = *(const float4*)&smA[l * 2 * C + C + L * 4];
        vs.x += fmaxf((a.x - b.x) * r.x - m.x, 0.f);
        vs.y += fmaxf((a.y - b.y) * r.y - m.y, 0.f);
        vs.z += fmaxf((a.z - b.z) * r.z - m.z, 0.f);
        vs.w += fmaxf((a.w - b.w) * r.w - m.w, 0.f);
    }
    float pr[16];
#pragma unroll
    for (int co = 0; co < CIN; co++) {
        const float4 w = *(const float4*)&KEc[co * C + L * 4];
        pr[co] = w.x * vs.x + w.y * vs.y + w.z * vs.z + w.w * vs.w;
    }
#pragma unroll
    for (int d = 1; d < 16; d <<= 1) {
#pragma unroll
        for (int co = 0; co < CIN; co++)
            pr[co] += __shfl_xor_sync(0xffffffffu, pr[co], d);
    }
    float xr = __ldg(&xe[(size_t)L * NE + e]);
    float acc = pr[L];
    int half = wl & 16;
#pragma unroll
    for (int c = 0; c < CIN; c++) {
        float xc = __shfl_sync(0xffffffffu, xr, half + c);
        acc += M2s[L * CIN + c] * xc;
    }
    out[(size_t)L * NE + e] = acc;
}

extern "C" void kernel_launch(void* const* d_in, const int* in_sizes, int n_in,
                              void* d_out, int out_size) {
    const float* xn      = (const float*)d_in[0];
    const float* xe      = (const float*)d_in[1];
    const int*   iInd    = (const int*)d_in[2];
    const int*   jInd    = (const int*)d_in[3];
    const float* KNopen  = (const float*)d_in[4];
    const float* KEopen  = (const float*)d_in[5];
    const float* KNclose = (const float*)d_in[6];
    const float* KEclose = (const float*)d_in[7];
    const float* KN      = (const float*)d_in[8];
    const float* KE      = (const float*)d_in[9];
    const float* KD      = (const float*)d_in[10];
    float* out = (float*)d_out;
    (void)in_sizes; (void)n_in; (void)out_size;

    float *pXn, *pZs, *pW, *pU, *pDiv;
    __half2* pZh;
    cudaGetSymbolAddress((void**)&pXn, g_Xn);
    cudaGetSymbolAddress((void**)&pZs, g_Zs);
    cudaGetSymbolAddress((void**)&pZh, g_Zh);
    cudaGetSymbolAddress((void**)&pW, g_W);
    cudaGetSymbolAddress((void**)&pU, g_U);
    cudaGetSymbolAddress((void**)&pDiv, g_div);

    const int TB = 256;
    const int gN = (NN + TB - 1) / TB;          // 196
    const int gE = (NE + TB - 1) / TB;          // 3125
    const int gMM = (NN * 2 + TB - 1) / TB;     // 391
    const int gCSR = (NN * 16 + TB - 1) / TB;   // 3125
    const int gEB = (NE * 16) / TB;             // 50000

    k_pre<<<gE, TB>>>();
    k_m2<<<1, TB>>>(KEclose, KEopen);
    k_deg<<<gE, TB>>>(iInd, jInd);
    k_bsum<<<NBLK, TB>>>();
    k_bscan<<<1, TB>>>();
    k_scan3<<<NBLK, TB>>>();
    k_fill<<<gE, TB>>>(iInd, jInd);
    k_open<<<gN, TB>>>(xn, KNopen, pXn, NN);
    k_edge0<<<gE, TB>>>(xe, iInd, jInd);
    k_expand<<<gN, TB>>>(KEopen);

    for (int l = 0; l < NL; l++) {
        const float* Kn = KN + (size_t)l * C * C;
        const float* Ke = KE + (size_t)l * C * C;
        const float* Kd = KD + (size_t)l * C * C;
        float* pZ = pZs + (size_t)l * NN * C;
        __half2* pZhl = pZh + (size_t)l * NN * 32;

        k_mmv3<1><<<gMM, TB>>>(pXn, Kn, pZ, pZhl, NN);
        k_mmv3<0><<<gMM, TB>>>(pXn, Kd, pW, nullptr, NN);
        k_stats<<<256, TB>>>(pW, NN, 2 * C);
        k_statsZ<<<gCSR, TB>>>(pZ, pZhl);
        k_scales0<<<1, TB>>>(l);
        k_divCSR<<<gCSR, TB>>>(pZhl, l);
        k_mmv3<0><<<gMM, TB>>>(pDiv, Ke, pU, nullptr, NN);
        k_stats<<<256, TB>>>(pU, NN, 4 * C);
        k_scales1<<<1, TB>>>();
        k_update<<<gN, TB>>>();
    }

    k_close<<<gN, TB>>>(KNclose, pXn, out, NN);
    k_closeMega<<<gEB, TB>>>(xe, KEclose, iInd, jInd, out + (size_t)CIN * NN);
}

// round 17
// speedup vs baseline: 1.1399x; 1.0915x over previous
#include <cuda_runtime.h>
#include <cuda_fp16.h>

#define NN 50000
#define NE 800000
#define C 64
#define CIN 16
#define NL 4
#define HSTEP 0.1f
#define EPSV 1e-3f

// ---- static device scratch ----
__device__ __align__(256) float g_Xn[NN * C];
__device__ __align__(256) float g_Zs[(size_t)NL * NN * C];    // per-layer Z (fp32)
__device__ __align__(256) __half2 g_Zh[(size_t)NL * NN * 32]; // fp16 mirror of Z
__device__ __align__(256) float g_W[NN * C];
__device__ __align__(256) float g_U[NN * C];
__device__ __align__(256) float g_div[NN * C];
__device__ __align__(256) float g_div16[NN * CIN];
__device__ __align__(256) float g_scr[6 * C];
__device__ __align__(256) float g_nrm[6 * C];
__device__ __align__(256) float g_nrmA[NL * 2 * C];
__device__ __align__(256) float g_M2[CIN * CIN];
// CSR
#define NBLK ((NN + 255) / 256)   // 196
__device__ int g_deg[NN];
__device__ int g_w[NN];
__device__ int g_off[NN + 1];
__device__ int g_cur[NN];
__device__ int g_adj[2 * NE];
__device__ int g_bsum[NBLK];
__device__ int g_boff[NBLK];

__device__ __forceinline__ void red4(float* p, float x, float y, float z, float w) {
    asm volatile("red.global.add.v4.f32 [%0], {%1,%2,%3,%4};"
                 :: "l"(p), "f"(x), "f"(y), "f"(z), "f"(w) : "memory");
}

__device__ __forceinline__ int wscan_incl(int v, int lane) {
#pragma unroll
    for (int d = 1; d < 32; d <<= 1) {
        int t = __shfl_up_sync(0xffffffffu, v, d);
        if (lane >= d) v += t;
    }
    return v;
}

__device__ __forceinline__ float4 ldZh(const __half2* Zh, size_t node, int L) {
    uint2 raw = __ldg((const uint2*)(Zh + node * 32 + L * 2));
    __half2 h0 = *(__half2*)&raw.x;
    __half2 h1 = *(__half2*)&raw.y;
    float2 f0 = __half22float2(h0);
    float2 f1 = __half22float2(h1);
    return make_float4(f0.x, f0.y, f1.x, f1.y);
}

__global__ void k_pre() {
    int t = blockIdx.x * blockDim.x + threadIdx.x;
    if (t < NN * CIN) g_div16[t] = 0.f;
    if (t < 6 * C) g_scr[t] = 0.f;
    if (t < NN) { g_deg[t] = 0; g_w[t] = 0; }
}

__global__ void k_deg(const int* __restrict__ iInd, const int* __restrict__ jInd) {
    int e = blockIdx.x * blockDim.x + threadIdx.x;
    if (e >= NE) return;
    int i = iInd[e], j = jInd[e];
    atomicAdd(&g_deg[i], 1);
    atomicAdd(&g_deg[j], 1);
    atomicAdd(&g_w[i], 1);
    atomicAdd(&g_w[j], -1);
}

__global__ void k_bsum() {
    int idx = blockIdx.x * 256 + threadIdx.x;
    int v = (idx < NN) ? g_deg[idx] : 0;
    int lane = threadIdx.x & 31, w = threadIdx.x >> 5;
#pragma unroll
    for (int d = 16; d > 0; d >>= 1) v += __shfl_down_sync(0xffffffffu, v, d);
    __shared__ int ws[8];
    if (lane == 0) ws[w] = v;
    __syncthreads();
    if (threadIdx.x == 0) {
        int s = 0;
#pragma unroll
        for (int k = 0; k < 8; k++) s += ws[k];
        g_bsum[blockIdx.x] = s;
    }
}

__global__ void k_bscan() {
    int t = threadIdx.x;
    int v = (t < NBLK) ? g_bsum[t] : 0;
    int lane = t & 31, w = t >> 5;
    int incl = wscan_incl(v, lane);
    __shared__ int ws[8];
    if (lane == 31) ws[w] = incl;
    __syncthreads();
    if (w == 0 && lane < 8) {
        int x = ws[lane];
#pragma unroll
        for (int d = 1; d < 8; d <<= 1) {
            int tt = __shfl_up_sync(0x000000ffu, x, d);
            if (lane >= d) x += tt;
        }
        ws[lane] = x;
    }
    __syncthreads();
    int pref = (w > 0) ? ws[w - 1] : 0;
    if (t < NBLK) g_boff[t] = pref + incl - v;
    if (t == 0) g_off[NN] = 2 * NE;
}

__global__ void k_scan3() {
    int idx = blockIdx.x * 256 + threadIdx.x;
    int v = (idx < NN) ? g_deg[idx] : 0;
    int lane = threadIdx.x & 31, w = threadIdx.x >> 5;
    int incl = wscan_incl(v, lane);
    __shared__ int ws[8];
    if (lane == 31) ws[w] = incl;
    __syncthreads();
    if (w == 0 && lane < 8) {
        int x = ws[lane];
#pragma unroll
        for (int d = 1; d < 8; d <<= 1) {
            int tt = __shfl_up_sync(0x000000ffu, x, d);
            if (lane >= d) x += tt;
        }
        ws[lane] = x;
    }
    __syncthreads();
    int pref = (w > 0) ? ws[w - 1] : 0;
    if (idx < NN) {
        int o = g_boff[blockIdx.x] + pref + incl - v;
        g_off[idx] = o;
        g_cur[idx] = o;
    }
}

__global__ void k_fill(const int* __restrict__ iInd, const int* __restrict__ jInd) {
    int e = blockIdx.x * blockDim.x + threadIdx.x;
    if (e >= NE) return;
    int i = iInd[e], j = jInd[e];
    int p = atomicAdd(&g_cur[i], 1);
    g_adj[p] = (j << 1);
    int q = atomicAdd(&g_cur[j], 1);
    g_adj[q] = (i << 1) | 1;
}

__global__ void k_m2(const float* __restrict__ KEc, const float* __restrict__ KEo) {
    int t = threadIdx.x;
    int co = t >> 4, ci = t & 15;
    float s = 0.f;
#pragma unroll
    for (int k = 0; k < C; k++) s += KEc[co * C + k] * KEo[k * CIN + ci];
    g_M2[co * CIN + ci] = s;
}

__global__ void k_open(const float* __restrict__ in, const float* __restrict__ K,
                       float* __restrict__ out, int count) {
    __shared__ __align__(16) float KT[CIN * C];
    for (int idx = threadIdx.x; idx < CIN * C; idx += blockDim.x) {
        int k = idx & (C - 1); int c = idx >> 6;
        KT[idx] = K[k * CIN + c];
    }
    __syncthreads();
    int n = blockIdx.x * blockDim.x + threadIdx.x;
    if (n >= count) return;
    float4 acc[C / 4];
#pragma unroll
    for (int q = 0; q < C / 4; q++) acc[q] = make_float4(0.f, 0.f, 0.f, 0.f);
#pragma unroll
    for (int c = 0; c < CIN; c++) {
        float v = __ldg(&in[(size_t)c * count + n]);
        const float4* w = (const float4*)&KT[c * C];
#pragma unroll
        for (int q = 0; q < C / 4; q++) {
            float4 t = w[q];
            acc[q].x += t.x * v; acc[q].y += t.y * v;
            acc[q].z += t.z * v; acc[q].w += t.w * v;
        }
    }
    float4* o = (float4*)&out[(size_t)n * C];
#pragma unroll
    for (int q = 0; q < C / 4; q++) o[q] = acc[q];
}

__global__ void k_edge0(const float* __restrict__ xe, const int* __restrict__ iInd,
                        const int* __restrict__ jInd) {
    int e = blockIdx.x * blockDim.x + threadIdx.x;
    if (e >= NE) return;
    int i = __ldg(&iInd[e]);
    int j = __ldg(&jInd[e]);
    float a[CIN];
#pragma unroll
    for (int c = 0; c < CIN; c++) a[c] = __ldg(&xe[(size_t)c * NE + e]);
    float* di = &g_div16[(size_t)i * CIN];
    float* dj = &g_div16[(size_t)j * CIN];
#pragma unroll
    for (int k = 0; k < 4; k++)
        red4(di + k * 4, a[k * 4], a[k * 4 + 1], a[k * 4 + 2], a[k * 4 + 3]);
#pragma unroll
    for (int k = 0; k < 4; k++)
        red4(dj + k * 4, -a[k * 4], -a[k * 4 + 1], -a[k * 4 + 2], -a[k * 4 + 3]);
}

__global__ void k_expand(const float* __restrict__ KEo) {
    __shared__ __align__(16) float KT[CIN * C];
    for (int idx = threadIdx.x; idx < CIN * C; idx += blockDim.x) {
        int k = idx & (C - 1); int c = idx >> 6;
        KT[idx] = KEo[k * CIN + c];
    }
    __syncthreads();
    int n = blockIdx.x * blockDim.x + threadIdx.x;
    if (n >= NN) return;
    float d[CIN];
#pragma unroll
    for (int k = 0; k < 4; k++)
        *(float4*)&d[k * 4] = *(const float4*)&g_div16[(size_t)n * CIN + k * 4];
    float4 acc[C / 4];
#pragma unroll
    for (int q = 0; q < C / 4; q++) acc[q] = make_float4(0.f, 0.f, 0.f, 0.f);
#pragma unroll
    for (int c = 0; c < CIN; c++) {
        float v = d[c];
        const float4* w = (const float4*)&KT[c * C];
#pragma unroll
        for (int q = 0; q < C / 4; q++) {
            float4 t = w[q];
            acc[q].x += t.x * v; acc[q].y += t.y * v;
            acc[q].z += t.z * v; acc[q].w += t.w * v;
        }
    }
    float4* o = (float4*)&g_div[(size_t)n * C];
#pragma unroll
    for (int q = 0; q < C / 4; q++) o[q] = acc[q];
}

// matmul: 2 nodes x 16 outputs per thread, padded conflict-free layout.
// WH=1: also write fp16 mirror.  STATS=1: fused per-channel sum/sumsq into g_scr[soff..soff+2C).
template <int WH, int STATS>
__global__ void k_mmv3(const float* __restrict__ In, const float* __restrict__ M,
                       float* __restrict__ Out, __half2* __restrict__ OutH,
                       int count, int soff) {
    __shared__ __align__(16) float MT[C * 80];
    __shared__ float redS[8 * 64];
    __shared__ float redQ[8 * 64];
    for (int idx = threadIdx.x; idx < C * C; idx += 256) {
        int k = idx & (C - 1); int c = idx >> 6;
        MT[c * 80 + (k >> 4) * 20 + (k & 15)] = M[k * C + c];
    }
    __syncthreads();
    int t = blockIdx.x * 256 + threadIdx.x;
    int p = t >> 2;
    int q = t & 3;
    int n0 = p * 2;
    bool valid = (n0 < count);   // count even -> n0+1 valid iff n0 valid
    float4 b0 = make_float4(0.f, 0.f, 0.f, 0.f), b1 = b0, b2 = b0, b3 = b0;
    float4 d0 = b0, d1 = b0, d2 = b0, d3 = b0;
    if (valid) {
        const float4* r0 = (const float4*)&In[(size_t)n0 * C];
        const float4* r1 = (const float4*)&In[(size_t)(n0 + 1) * C];
#pragma unroll
        for (int c4 = 0; c4 < 16; c4++) {
            float4 u = __ldg(&r0[c4]);
            float4 v = __ldg(&r1[c4]);
#pragma unroll
            for (int cc = 0; cc < 4; cc++) {
                float su = (cc == 0) ? u.x : (cc == 1) ? u.y : (cc == 2) ? u.z : u.w;
                float sv = (cc == 0) ? v.x : (cc == 1) ? v.y : (cc == 2) ? v.z : v.w;
                const float4* w = (const float4*)&MT[(c4 * 4 + cc) * 80 + q * 20];
                float4 w0 = w[0], w1 = w[1], w2 = w[2], w3 = w[3];
                b0.x += w0.x * su; b0.y += w0.y * su; b0.z += w0.z * su; b0.w += w0.w * su;
                b1.x += w1.x * su; b1.y += w1.y * su; b1.z += w1.z * su; b1.w += w1.w * su;
                b2.x += w2.x * su; b2.y += w2.y * su; b2.z += w2.z * su; b2.w += w2.w * su;
                b3.x += w3.x * su; b3.y += w3.y * su; b3.z += w3.z * su; b3.w += w3.w * su;
                d0.x += w0.x * sv; d0.y += w0.y * sv; d0.z += w0.z * sv; d0.w += w0.w * sv;
                d1.x += w1.x * sv; d1.y += w1.y * sv; d1.z += w1.z * sv; d1.w += w1.w * sv;
                d2.x += w2.x * sv; d2.y += w2.y * sv; d2.z += w2.z * sv; d2.w += w2.w * sv;
                d3.x += w3.x * sv; d3.y += w3.y * sv; d3.z += w3.z * sv; d3.w += w3.w * sv;
            }
        }
        float4* o0 = (float4*)&Out[(size_t)n0 * C + q * 16];
        o0[0] = b0; o0[1] = b1; o0[2] = b2; o0[3] = b3;
        float4* o1 = (float4*)&Out[(size_t)(n0 + 1) * C + q * 16];
        o1[0] = d0; o1[1] = d1; o1[2] = d2; o1[3] = d3;
        if (WH) {
            __align__(16) __half2 h[8];
            h[0] = __floats2half2_rn(b0.x, b0.y); h[1] = __floats2half2_rn(b0.z, b0.w);
            h[2] = __floats2half2_rn(b1.x, b1.y); h[3] = __floats2half2_rn(b1.z, b1.w);
            h[4] = __floats2half2_rn(b2.x, b2.y); h[5] = __floats2half2_rn(b2.z, b2.w);
            h[6] = __floats2half2_rn(b3.x, b3.y); h[7] = __floats2half2_rn(b3.z, b3.w);
            *(uint4*)&OutH[(size_t)n0 * 32 + q * 8] = *(uint4*)h;
            h[0] = __floats2half2_rn(d0.x, d0.y); h[1] = __floats2half2_rn(d0.z, d0.w);
            h[2] = __floats2half2_rn(d1.x, d1.y); h[3] = __floats2half2_rn(d1.z, d1.w);
            h[4] = __floats2half2_rn(d2.x, d2.y); h[5] = __floats2half2_rn(d2.z, d2.w);
            h[6] = __floats2half2_rn(d3.x, d3.y); h[7] = __floats2half2_rn(d3.z, d3.w);
            *(uint4*)&OutH[(size_t)(n0 + 1) * 32 + q * 8] = *(uint4*)h;
        }
    }
    if (STATS) {
        // per-thread channel sums over its 2 nodes (zeros when invalid)
        float s16[16], q16[16];
        s16[0] = b0.x + d0.x; s16[1] = b0.y + d0.y; s16[2] = b0.z + d0.z; s16[3] = b0.w + d0.w;
        s16[4] = b1.x + d1.x; s16[5] = b1.y + d1.y; s16[6] = b1.z + d1.z; s16[7] = b1.w + d1.w;
        s16[8] = b2.x + d2.x; s16[9] = b2.y + d2.y; s16[10] = b2.z + d2.z; s16[11] = b2.w + d2.w;
        s16[12] = b3.x + d3.x; s16[13] = b3.y + d3.y; s16[14] = b3.z + d3.z; s16[15] = b3.w + d3.w;
        q16[0] = b0.x * b0.x + d0.x * d0.x; q16[1] = b0.y * b0.y + d0.y * d0.y;
        q16[2] = b0.z * b0.z + d0.z * d0.z; q16[3] = b0.w * b0.w + d0.w * d0.w;
        q16[4] = b1.x * b1.x + d1.x * d1.x; q16[5] = b1.y * b1.y + d1.y * d1.y;
        q16[6] = b1.z * b1.z + d1.z * d1.z; q16[7] = b1.w * b1.w + d1.w * d1.w;
        q16[8] = b2.x * b2.x + d2.x * d2.x; q16[9] = b2.y * b2.y + d2.y * d2.y;
        q16[10] = b2.z * b2.z + d2.z * d2.z; q16[11] = b2.w * b2.w + d2.w * d2.w;
        q16[12] = b3.x * b3.x + d3.x * d3.x; q16[13] = b3.y * b3.y + d3.y * d3.y;
        q16[14] = b3.z * b3.z + d3.z * d3.z; q16[15] = b3.w * b3.w + d3.w * d3.w;
        // reduce across same-q lanes (masks 4, 8, 16)
#pragma unroll
        for (int d = 4; d < 32; d <<= 1) {
#pragma unroll
            for (int i = 0; i < 16; i++) {
                s16[i] += __shfl_xor_sync(0xffffffffu, s16[i], d);
                q16[i] += __shfl_xor_sync(0xffffffffu, q16[i], d);
            }
        }
        int lane = threadIdx.x & 31, w = threadIdx.x >> 5;
        if (lane < 4) {
#pragma unroll
            for (int i = 0; i < 16; i++) {
                redS[w * 64 + lane * 16 + i] = s16[i];
                redQ[w * 64 + lane * 16 + i] = q16[i];
            }
        }
        __syncthreads();
        int tx = threadIdx.x;
        if (tx < 64) {
            float s = 0.f;
#pragma unroll
            for (int w2 = 0; w2 < 8; w2++) s += redS[w2 * 64 + tx];
            atomicAdd(&g_scr[soff + tx], s);
        } else if (tx < 128) {
            int ch = tx - 64;
            float s = 0.f;
#pragma unroll
            for (int w2 = 0; w2 < 8; w2++) s += redQ[w2 * 64 + ch];
            atomicAdd(&g_scr[soff + C + ch], s);
        }
    }
}

// CSR stats, 16 threads/node; T gathered from fp16 mirror
__global__ void k_statsZ(const float* __restrict__ Z, const __half2* __restrict__ Zh) {
    __shared__ float ss[C], sq[C];
    if (threadIdx.x < C) { ss[threadIdx.x] = 0.f; sq[threadIdx.x] = 0.f; }
    __syncthreads();
    int t = blockIdx.x * 256 + threadIdx.x;
    int n = t >> 4, L = t & 15;
    if (n < NN) {
        float4 zn = *(const float4*)&Z[(size_t)n * C + L * 4];
        float wf = (float)g_w[n];
        float df = (float)g_deg[n];
        float4 T = make_float4(0.f, 0.f, 0.f, 0.f);
        int k1 = g_off[n + 1];
        for (int k = g_off[n]; k < k1; k++) {
            int a = g_adj[k];
            if (!(a & 1)) {
                float4 zm = ldZh(Zh, (size_t)(a >> 1), L);
                T.x += zm.x; T.y += zm.y; T.z += zm.z; T.w += zm.w;
            }
        }
        float4 s4, q4;
        s4.x = wf * zn.x; s4.y = wf * zn.y; s4.z = wf * zn.z; s4.w = wf * zn.w;
        q4.x = df * zn.x * zn.x - 2.f * zn.x * T.x;
        q4.y = df * zn.y * zn.y - 2.f * zn.y * T.y;
        q4.z = df * zn.z * zn.z - 2.f * zn.z * T.z;
        q4.w = df * zn.w * zn.w - 2.f * zn.w * T.w;
        int ch = L * 4;
        atomicAdd(&ss[ch + 0], s4.x); atomicAdd(&ss[ch + 1], s4.y);
        atomicAdd(&ss[ch + 2], s4.z); atomicAdd(&ss[ch + 3], s4.w);
        atomicAdd(&sq[ch + 0], q4.x); atomicAdd(&sq[ch + 1], q4.y);
        atomicAdd(&sq[ch + 2], q4.z); atomicAdd(&sq[ch + 3], q4.w);
    }
    __syncthreads();
    if (threadIdx.x < C) {
        atomicAdd(&g_scr[threadIdx.x], ss[threadIdx.x]);
        atomicAdd(&g_scr[C + threadIdx.x], sq[threadIdx.x]);
    }
}

// scales0: A-norm -> g_nrmA[l]; W-norm -> g_nrm[2C..4C); then zero ALL scr (U slot is
// consumed by k_updateF of the PREVIOUS layer before this runs; this layer's mmKe
// writes U stats AFTER this kernel).
__global__ void k_scales0(int l) {
    int c = threadIdx.x;
    if (c < C) {
        float s = g_scr[c], q = g_scr[C + c];
        float m = s / (float)NE;
        float rH = HSTEP / sqrtf(fmaxf(q - s * m, 0.f) + EPSV);
        g_nrmA[l * 2 * C + c] = m * rH;
        g_nrmA[l * 2 * C + C + c] = rH;
        s = g_scr[2 * C + c]; q = g_scr[3 * C + c];
        m = s / (float)NN;
        g_nrm[2 * C + c] = m;
        g_nrm[3 * C + c] = 1.f / sqrtf(fmaxf(q - s * m, 0.f) + EPSV);
    }
    __syncthreads();
    for (int i = threadIdx.x; i < 6 * C; i += 256) g_scr[i] = 0.f;
}

// CSR divergence, 16 threads/node, branch-free, fp16 gathers
__global__ void k_divCSR(const __half2* __restrict__ Zh, int l) {
    __shared__ __align__(16) float sm[2 * C];
    if (threadIdx.x < 2 * C) sm[threadIdx.x] = g_nrmA[l * 2 * C + threadIdx.x];
    __syncthreads();
    int t = blockIdx.x * 256 + threadIdx.x;
    int n = t >> 4, L = t & 15;
    if (n >= NN) return;
    float4 zn = ldZh(Zh, (size_t)n, L);
    float4 mm = *(const float4*)&sm[L * 4];
    float4 rr = *(const float4*)&sm[C + L * 4];
    float4 acc = make_float4(0.f, 0.f, 0.f, 0.f);
    int k1 = g_off[n + 1];
    for (int k = g_off[n]; k < k1; k++) {
        int a = g_adj[k];
        float s = (a & 1) ? -1.f : 1.f;
        float4 zm = ldZh(Zh, (size_t)(a >> 1), L);
        acc.x += s * fmaxf(s * (zn.x - zm.x) * rr.x - mm.x, 0.f);
        acc.y += s * fmaxf(s * (zn.y - zm.y) * rr.y - mm.y, 0.f);
        acc.z += s * fmaxf(s * (zn.z - zm.z) * rr.z - mm.z, 0.f);
        acc.w += s * fmaxf(s * (zn.w - zm.w) * rr.w - mm.w, 0.f);
    }
    float4* dv = (float4*)&g_div[(size_t)n * C + L * 4];
    float4 d = *dv;
    d.x += acc.x; d.y += acc.y; d.z += acc.z; d.w += acc.w;
    *dv = d;
}

// update with inline U-scales: reads g_scr[4C..6C) directly
__global__ void k_updateF() {
    __shared__ __align__(16) float sm[4 * C];  // mW rW mU rU
    int tx = threadIdx.x;
    if (tx < C) {
        sm[tx]     = g_nrm[2 * C + tx];
        sm[C + tx] = g_nrm[3 * C + tx];
        float s = g_scr[4 * C + tx], q = g_scr[5 * C + tx];
        float m = s / (float)NN;
        sm[2 * C + tx] = m;
        sm[3 * C + tx] = 1.f / sqrtf(fmaxf(q - s * m, 0.f) + EPSV);
    }
    __syncthreads();
    int n = blockIdx.x * blockDim.x + tx;
    if (n >= NN) return;
#pragma unroll
    for (int q = 0; q < 16; q++) {
        float4 u = *(const float4*)&g_U[(size_t)n * C + q * 4];
        float4 w = *(const float4*)&g_W[(size_t)n * C + q * 4];
        float4 x = *(float4*)&g_Xn[(size_t)n * C + q * 4];
        float4 mw = *(const float4*)&sm[q * 4];
        float4 rw = *(const float4*)&sm[C + q * 4];
        float4 mu = *(const float4*)&sm[2 * C + q * 4];
        float4 ru = *(const float4*)&sm[3 * C + q * 4];
        x.x -= HSTEP * (fmaxf((u.x - mu.x) * ru.x, 0.f) + fmaxf((w.x - mw.x) * rw.x, 0.f));
        x.y -= HSTEP * (fmaxf((u.y - mu.y) * ru.y, 0.f) + fmaxf((w.y - mw.y) * rw.y, 0.f));
        x.z -= HSTEP * (fmaxf((u.z - mu.z) * ru.z, 0.f) + fmaxf((w.z - mw.z) * rw.z, 0.f));
        x.w -= HSTEP * (fmaxf((u.w - mu.w) * ru.w, 0.f) + fmaxf((w.w - mw.w) * rw.w, 0.f));
        *(float4*)&g_Xn[(size_t)n * C + q * 4] = x;
    }
}

__global__ void k_close(const float* __restrict__ Kc, const float* __restrict__ In,
                        float* __restrict__ out, int count) {
    __shared__ __align__(16) float Ks[CIN * C];
    for (int idx = threadIdx.x; idx < CIN * C; idx += blockDim.x) Ks[idx] = Kc[idx];
    __syncthreads();
    int n = blockIdx.x * blockDim.x + threadIdx.x;
    if (n >= count) return;
    float4 row[16];
#pragma unroll
    for (int q = 0; q < 16; q++)
        row[q] = __ldg((const float4*)&In[(size_t)n * C + q * 4]);
#pragma unroll
    for (int co = 0; co < CIN; co++) {
        float acc = 0.f;
#pragma unroll
        for (int q = 0; q < 16; q++) {
            float4 w = *(const float4*)&Ks[co * C + q * 4];
            acc += w.x * row[q].x + w.y * row[q].y + w.z * row[q].z + w.w * row[q].w;
        }
        out[(size_t)co * count + n] = acc;
    }
}

__global__ void k_closeMega(const float* __restrict__ xe, const float* __restrict__ KEclose,
                            const int* __restrict__ iInd, const int* __restrict__ jInd,
                            float* __restrict__ out) {
    __shared__ __align__(16) float KEc[CIN * C];
    __shared__ __align__(16) float smA[NL * 2 * C];
    __shared__ float M2s[CIN * CIN];
    int tx = threadIdx.x;
    for (int idx = tx; idx < CIN * C; idx += 256) KEc[idx] = KEclose[idx];
    for (int idx = tx; idx < NL * 2 * C; idx += 256) smA[idx] = g_nrmA[idx];
    if (tx < CIN * CIN) M2s[tx] = g_M2[tx];
    __syncthreads();
    int t = blockIdx.x * 256 + tx;
    int e = t >> 4;
    int L = t & 15;
    int wl = tx & 31;
    int i = __ldg(&iInd[e]);
    int j = __ldg(&jInd[e]);
    float4 vs = make_float4(0.f, 0.f, 0.f, 0.f);
#pragma unroll
    for (int l = 0; l < NL; l++) {
        const __half2* Zh = g_Zh + (size_t)l * NN * 32;
        float4 a = ldZh(Zh, (size_t)i, L);
        float4 b = ldZh(Zh, (size_t)j, L);
        float4 m = *(const float4*)&smA[l * 2 * C + L * 4];
        float4 r = *(const float4*)&smA[l * 2 * C + C + L * 4];
        vs.x += fmaxf((a.x - b.x) * r.x - m.x, 0.f);
        vs.y += fmaxf((a.y - b.y) * r.y - m.y, 0.f);
        vs.z += fmaxf((a.z - b.z) * r.z - m.z, 0.f);
        vs.w += fmaxf((a.w - b.w) * r.w - m.w, 0.f);
    }
    float pr[16];
#pragma unroll
    for (int co = 0; co < CIN; co++) {
        const float4 w = *(const float4*)&KEc[co * C + L * 4];
        pr[co] = w.x * vs.x + w.y * vs.y + w.z * vs.z + w.w * vs.w;
    }
#pragma unroll
    for (int d = 1; d < 16; d <<= 1) {
#pragma unroll
        for (int co = 0; co < CIN; co++)
            pr[co] += __shfl_xor_sync(0xffffffffu, pr[co], d);
    }
    float xr = __ldg(&xe[(size_t)L * NE + e]);
    float acc = pr[L];
    int half = wl & 16;
#pragma unroll
    for (int c = 0; c < CIN; c++) {
        float xc = __shfl_sync(0xffffffffu, xr, half + c);
        acc += M2s[L * CIN + c] * xc;
    }
    out[(size_t)L * NE + e] = acc;
}

extern "C" void kernel_launch(void* const* d_in, const int* in_sizes, int n_in,
                              void* d_out, int out_size) {
    const float* xn      = (const float*)d_in[0];
    const float* xe      = (const float*)d_in[1];
    const int*   iInd    = (const int*)d_in[2];
    const int*   jInd    = (const int*)d_in[3];
    const float* KNopen  = (const float*)d_in[4];
    const float* KEopen  = (const float*)d_in[5];
    const float* KNclose = (const float*)d_in[6];
    const float* KEclose = (const float*)d_in[7];
    const float* KN      = (const float*)d_in[8];
    const float* KE      = (const float*)d_in[9];
    const float* KD      = (const float*)d_in[10];
    float* out = (float*)d_out;
    (void)in_sizes; (void)n_in; (void)out_size;

    float *pXn, *pZs, *pW, *pU, *pDiv;
    __half2* pZh;
    cudaGetSymbolAddress((void**)&pXn, g_Xn);
    cudaGetSymbolAddress((void**)&pZs, g_Zs);
    cudaGetSymbolAddress((void**)&pZh, g_Zh);
    cudaGetSymbolAddress((void**)&pW, g_W);
    cudaGetSymbolAddress((void**)&pU, g_U);
    cudaGetSymbolAddress((void**)&pDiv, g_div);

    const int TB = 256;
    const int gN = (NN + TB - 1) / TB;          // 196
    const int gE = (NE + TB - 1) / TB;          // 3125
    const int gMM = (NN * 2 + TB - 1) / TB;     // 391
    const int gCSR = (NN * 16 + TB - 1) / TB;   // 3125
    const int gEB = (NE * 16) / TB;             // 50000

    k_pre<<<gE, TB>>>();
    k_m2<<<1, TB>>>(KEclose, KEopen);
    k_deg<<<gE, TB>>>(iInd, jInd);
    k_bsum<<<NBLK, TB>>>();
    k_bscan<<<1, TB>>>();
    k_scan3<<<NBLK, TB>>>();
    k_fill<<<gE, TB>>>(iInd, jInd);
    k_open<<<gN, TB>>>(xn, KNopen, pXn, NN);
    k_edge0<<<gE, TB>>>(xe, iInd, jInd);
    k_expand<<<gN, TB>>>(KEopen);

    for (int l = 0; l < NL; l++) {
        const float* Kn = KN + (size_t)l * C * C;
        const float* Ke = KE + (size_t)l * C * C;
        const float* Kd = KD + (size_t)l * C * C;
        float* pZ = pZs + (size_t)l * NN * C;
        __half2* pZhl = pZh + (size_t)l * NN * 32;

        k_mmv3<1, 0><<<gMM, TB>>>(pXn, Kn, pZ, pZhl, NN, 0);
        k_mmv3<0, 1><<<gMM, TB>>>(pXn, Kd, pW, nullptr, NN, 2 * C);
        k_statsZ<<<gCSR, TB>>>(pZ, pZhl);
        k_scales0<<<1, TB>>>(l);
        k_divCSR<<<gCSR, TB>>>(pZhl, l);
        k_mmv3<0, 1><<<gMM, TB>>>(pDiv, Ke, pU, nullptr, NN, 4 * C);
        k_updateF<<<gN, TB>>>();
    }

    k_close<<<gN, TB>>>(KNclose, pXn, out, NN);
    k_closeMega<<<gEB, TB>>>(xe, KEclose, iInd, jInd, out + (size_t)CIN * NN);
}